// round 4
// baseline (speedup 1.0000x reference)
#include <cuda_runtime.h>
#include <cstdint>
#include <math.h>

#define NB 16384
#define NLOC 12
#define NF 512
#define NH 256
#define SCALE 0.0625f

// Scratch (device globals: allocation-free rule)
__device__ float g_T[(size_t)NB * NF];       // 32 MB
__device__ float g_pooled[(size_t)NB * NF];  // 32 MB
__device__ float g_lfG[(size_t)NB * NF];     // 32 MB
__device__ float g_M3[NF * NF];              // Wq @ Wk^T
__device__ float g_Mcat[2 * NF * NF];        // [Wv@Wf_top ; S*Wv@Wf_bot]
__device__ float g_c[NF];
__device__ float g_S;

__device__ __forceinline__ uint32_t f2tf(float x) {
    uint32_t y;
    asm("cvt.rna.tf32.f32 %0, %1;" : "=r"(y) : "f"(x));
    return y;
}

__device__ __forceinline__ void cpa16(void* dst_smem, const void* src) {
    uint32_t d = (uint32_t)__cvta_generic_to_shared(dst_smem);
    asm volatile("cp.async.cg.shared.global [%0], [%1], 16;" :: "r"(d), "l"(src));
}
__device__ __forceinline__ void cpa_commit() {
    asm volatile("cp.async.commit_group;");
}
template <int N>
__device__ __forceinline__ void cpa_wait() {
    asm volatile("cp.async.wait_group %0;" :: "n"(N));
}

__device__ __forceinline__ void mma8(float* c, const uint32_t* a, const uint32_t* b) {
    asm volatile(
        "mma.sync.aligned.m16n8k8.row.col.f32.tf32.tf32.f32 "
        "{%0,%1,%2,%3}, {%4,%5,%6,%7}, {%8,%9}, {%0,%1,%2,%3};"
        : "+f"(c[0]), "+f"(c[1]), "+f"(c[2]), "+f"(c[3])
        : "r"(a[0]), "r"(a[1]), "r"(a[2]), "r"(a[3]), "r"(b[0]), "r"(b[1]));
}

// Generic tf32 GEMM: C[M,N] = A[M,K] @ B[K,N]  (B row-major, or B^T if BT: Bsrc is [N,K])
// CONCAT: A rows are [A | A2] along K (split at NF).
// FUSE:   C = relu(acc + cvec[n]) + lfG[m,n]   (final output epilogue)
// 2-stage cp.async double-buffered mainloop; tf32 conversion on consume.
// Grid: x = N-tile (fast-varying -> A tile reused across consecutive blocks),
//       y = M-tile.  __launch_bounds__(256,2): guarantee 2 CTAs/SM.
template <bool BT, bool CONCAT, bool FUSE>
__global__ __launch_bounds__(256, 2) void gemm_tf32(
    const float* __restrict__ A, int lda,
    const float* __restrict__ A2,
    const float* __restrict__ B, int ldb,
    float* __restrict__ C, int ldc,
    int K,
    const float* __restrict__ alpha_ptr,
    const float* __restrict__ cvec,
    const float* __restrict__ lfG)
{
    constexpr int BM = 128, BN = 64, BK = 16;
    constexpr int ASTR = 20;  // floats per A smem row (bank-conflict-free frag loads)
    constexpr int BSTR = 72;  // floats per B smem row (72 mod 32 == 8 -> conflict-free)
    __shared__ float As[2][BM][ASTR];
    __shared__ float Bs[2][BK][BSTR];

    const int tid = threadIdx.x;
    const int m0 = blockIdx.y * BM;   // M from y
    const int n0 = blockIdx.x * BN;   // N from x (fastest-varying)
    const int warp = tid >> 5, lane = tid & 31;
    const int wm = warp & 3, wn = warp >> 2;   // 4 x 2 warp grid, 32x32 warp tile
    const int grp = lane >> 2, qid = lane & 3;

    // Per-thread load coordinates (constant across iterations)
    const int ar0 = tid >> 2, ac0 = (tid & 3) * 4;          // A: 2 float4 / thread
    const int ar1 = (tid + 256) >> 2;
    const int bk0 = tid >> 4, bn0 = (tid & 15) * 4;         // B (!BT): 1 float4 / thread
    const int tn = tid >> 2, tk = (tid & 3) * 4;            // B (BT)

    float acc[2][4][4];
#pragma unroll
    for (int i = 0; i < 2; i++)
#pragma unroll
        for (int j = 0; j < 4; j++)
#pragma unroll
            for (int l = 0; l < 4; l++) acc[i][j][l] = 0.f;

    const int niter = K / BK;

    // ---- tile issue ----
    auto issue = [&](int s, int k0) {
        const float* Ap = A;
        int kA = k0;
        if (CONCAT && k0 >= NF) { Ap = A2; kA = k0 - NF; }
        cpa16(&As[s][ar0][ac0], Ap + (size_t)(m0 + ar0) * lda + kA + ac0);
        cpa16(&As[s][ar1][ac0], Ap + (size_t)(m0 + ar1) * lda + kA + ac0);
        if (!BT) {
            cpa16(&Bs[s][bk0][bn0], B + (size_t)(k0 + bk0) * ldb + n0 + bn0);
        } else {
            float4 v = *(const float4*)(B + (size_t)(n0 + tn) * ldb + k0 + tk);
            Bs[s][tk + 0][tn] = v.x;
            Bs[s][tk + 1][tn] = v.y;
            Bs[s][tk + 2][tn] = v.z;
            Bs[s][tk + 3][tn] = v.w;
        }
        cpa_commit();
    };

    issue(0, 0);

    for (int it = 0; it < niter; it++) {
        const int cur = it & 1;
        if (it + 1 < niter) {
            issue(cur ^ 1, (it + 1) * BK);
            cpa_wait<1>();
        } else {
            cpa_wait<0>();
        }
        __syncthreads();

#pragma unroll
        for (int kk = 0; kk < BK; kk += 8) {
            uint32_t a[2][4], b[4][2];
#pragma unroll
            for (int mi = 0; mi < 2; mi++) {
                int m = wm * 32 + mi * 16;
                a[mi][0] = f2tf(As[cur][m + grp][kk + qid]);
                a[mi][1] = f2tf(As[cur][m + grp + 8][kk + qid]);
                a[mi][2] = f2tf(As[cur][m + grp][kk + qid + 4]);
                a[mi][3] = f2tf(As[cur][m + grp + 8][kk + qid + 4]);
            }
#pragma unroll
            for (int ni = 0; ni < 4; ni++) {
                int n = wn * 32 + ni * 8;
                b[ni][0] = f2tf(Bs[cur][kk + qid][n + grp]);
                b[ni][1] = f2tf(Bs[cur][kk + qid + 4][n + grp]);
            }
#pragma unroll
            for (int mi = 0; mi < 2; mi++)
#pragma unroll
                for (int ni = 0; ni < 4; ni++) mma8(acc[mi][ni], a[mi], b[ni]);
        }
        __syncthreads();
    }

    float alpha = (!FUSE && alpha_ptr) ? *alpha_ptr : 1.f;
#pragma unroll
    for (int mi = 0; mi < 2; mi++) {
#pragma unroll
        for (int ni = 0; ni < 4; ni++) {
            int r = m0 + wm * 32 + mi * 16 + grp;
            int cn = n0 + wn * 32 + ni * 8 + qid * 2;
            size_t o0 = (size_t)r * ldc + cn;
            size_t o1 = (size_t)(r + 8) * ldc + cn;
            if (!FUSE) {
                float2 v0 = make_float2(alpha * acc[mi][ni][0], alpha * acc[mi][ni][1]);
                float2 v1 = make_float2(alpha * acc[mi][ni][2], alpha * acc[mi][ni][3]);
                *(float2*)(C + o0) = v0;
                *(float2*)(C + o1) = v1;
            } else {
                float c0 = cvec[cn], c1 = cvec[cn + 1];
                float2 v0, v1;
                v0.x = fmaxf(acc[mi][ni][0] + c0, 0.f) + lfG[o0];
                v0.y = fmaxf(acc[mi][ni][1] + c1, 0.f) + lfG[o0 + 1];
                v1.x = fmaxf(acc[mi][ni][2] + c0, 0.f) + lfG[o1];
                v1.y = fmaxf(acc[mi][ni][3] + c1, 0.f) + lfG[o1 + 1];
                *(float2*)(C + o0) = v0;
                *(float2*)(C + o1) = v1;
            }
        }
    }
}

// Per-row: scores vs T, softmax over 12, pooled = sum a_k * local_k,
// lfG = sum w_dr_k * local_k + b_dr + G   (local read exactly once via smem)
__global__ __launch_bounds__(128) void k_attn(
    const float* __restrict__ G, const float* __restrict__ L,
    const float* __restrict__ wdr, const float* __restrict__ bdr)
{
    __shared__ float4 sL[NLOC * 128];
    __shared__ float4 sT[128];
    __shared__ float sd[NLOC];
    const int b = blockIdx.x, tid = threadIdx.x;
    const float4* Lr = (const float4*)(L + (size_t)b * NLOC * NF);
    sT[tid] = ((const float4*)(g_T + (size_t)b * NF))[tid];
#pragma unroll
    for (int k = 0; k < NLOC; k++) sL[k * 128 + tid] = Lr[k * 128 + tid];
    __syncthreads();

    const int warp = tid >> 5, lane = tid & 31;
#pragma unroll
    for (int kk = 0; kk < 3; kk++) {
        int k = warp * 3 + kk;
        float s = 0.f;
#pragma unroll
        for (int j = 0; j < 4; j++) {
            float4 x = sL[k * 128 + lane + j * 32];
            float4 t = sT[lane + j * 32];
            s += x.x * t.x + x.y * t.y + x.z * t.z + x.w * t.w;
        }
#pragma unroll
        for (int o = 16; o; o >>= 1) s += __shfl_xor_sync(0xffffffffu, s, o);
        if (lane == 0) sd[k] = s;
    }
    __syncthreads();

    float a[NLOC], mx = -1e30f;
#pragma unroll
    for (int k = 0; k < NLOC; k++) mx = fmaxf(mx, sd[k]);
    float sum = 0.f;
#pragma unroll
    for (int k = 0; k < NLOC; k++) { a[k] = expf((sd[k] - mx) * SCALE); sum += a[k]; }
    float inv = 1.f / sum;

    float4 p = make_float4(0, 0, 0, 0), q = make_float4(0, 0, 0, 0);
#pragma unroll
    for (int k = 0; k < NLOC; k++) {
        float ak = a[k] * inv, wk = wdr[k];
        float4 x = sL[k * 128 + tid];
        p.x += ak * x.x; p.y += ak * x.y; p.z += ak * x.z; p.w += ak * x.w;
        q.x += wk * x.x; q.y += wk * x.y; q.z += wk * x.z; q.w += wk * x.w;
    }
    float bd = *bdr;
    float4 g = ((const float4*)(G + (size_t)b * NF))[tid];
    ((float4*)(g_pooled + (size_t)b * NF))[tid] = p;
    float4 o;
    o.x = q.x + bd + g.x; o.y = q.y + bd + g.y;
    o.z = q.z + bd + g.z; o.w = q.w + bd + g.w;
    ((float4*)(g_lfG + (size_t)b * NF))[tid] = o;
}

// c[f'] = bf + bv@Wf_top + S*bv@Wf_bot + b_dr*colsum(Wf_bot); also writes g_S
__global__ void k_cvec(const float* __restrict__ bv, const float* __restrict__ Wf,
                       const float* __restrict__ bf, const float* __restrict__ wdr,
                       const float* __restrict__ bdr)
{
    int f = threadIdx.x;  // 512 threads
    float S = 0.f;
#pragma unroll
    for (int k = 0; k < NLOC; k++) S += wdr[k];
    if (f == 0) g_S = S;
    float a1 = 0.f, a2 = 0.f, a3 = 0.f;
    for (int h = 0; h < NH; h++) {
        float w1 = Wf[(size_t)h * NF + f];
        float w2 = Wf[(size_t)(NH + h) * NF + f];
        float bvh = bv[h];
        a1 += bvh * w1;
        a2 += bvh * w2;
        a3 += w2;
    }
    g_c[f] = bf[f] + a1 + S * a2 + (*bdr) * a3;
}

extern "C" void kernel_launch(void* const* d_in, const int* in_sizes, int n_in,
                              void* d_out, int out_size)
{
    const float* G   = (const float*)d_in[0];
    const float* L   = (const float*)d_in[1];
    const float* Wq  = (const float*)d_in[2];
    // d_in[3] = bq (unused: drops out of softmax)
    const float* Wk  = (const float*)d_in[4];
    // d_in[5] = bk (unused: k-independent score shift cancels in softmax)
    const float* Wv  = (const float*)d_in[6];
    const float* bv  = (const float*)d_in[7];
    const float* wdr = (const float*)d_in[8];
    const float* bdr = (const float*)d_in[9];
    const float* Wf  = (const float*)d_in[10];
    const float* bf  = (const float*)d_in[11];
    float* out = (float*)d_out;

    float *T, *P, *LF, *M3, *Mcat, *cvec, *Sp;
    cudaGetSymbolAddress((void**)&T, g_T);
    cudaGetSymbolAddress((void**)&P, g_pooled);
    cudaGetSymbolAddress((void**)&LF, g_lfG);
    cudaGetSymbolAddress((void**)&M3, g_M3);
    cudaGetSymbolAddress((void**)&Mcat, g_Mcat);
    cudaGetSymbolAddress((void**)&cvec, g_c);
    cudaGetSymbolAddress((void**)&Sp, g_S);

    dim3 blk(256);
    dim3 gsmall(NF / 64, NF / 128);   // x = N-tiles (8), y = M-tiles (4)
    dim3 gbig(NF / 64, NB / 128);     // x = N-tiles (8), y = M-tiles (128)

    // 0) constants: S and c
    k_cvec<<<1, NF>>>(bv, Wf, bf, wdr, bdr);

    // 1) M3 = Wq @ Wk^T   (A = Wq [512,256], B^T from Wk [512,256])
    gemm_tf32<true, false, false><<<gsmall, blk>>>(
        Wq, NH, nullptr, Wk, NH, M3, NF, NH, nullptr, nullptr, nullptr);

    // 2) Mcat_top = Wv @ Wf[0:256,:]
    gemm_tf32<false, false, false><<<gsmall, blk>>>(
        Wv, NH, nullptr, Wf, NF, Mcat, NF, NH, nullptr, nullptr, nullptr);

    // 3) Mcat_bot = S * (Wv @ Wf[256:512,:])
    gemm_tf32<false, false, false><<<gsmall, blk>>>(
        Wv, NH, nullptr, Wf + (size_t)NH * NF, NF, Mcat + (size_t)NF * NF, NF, NH,
        Sp, nullptr, nullptr);

    // 4) T = G @ M3   [16384,512] x [512,512]
    gemm_tf32<false, false, false><<<gbig, blk>>>(
        G, NF, nullptr, M3, NF, T, NF, NF, nullptr, nullptr, nullptr);

    // 5) per-row softmax / pooling (reads local_features once)
    k_attn<<<NB, 128>>>(G, L, wdr, bdr);

    // 6) OUT = relu([pooled | G] @ Mcat + c) + lfG   [16384,1024] x [1024,512]
    gemm_tf32<false, true, true><<<gbig, blk>>>(
        P, NF, G, Mcat, NF, out, NF, 2 * NF, nullptr, cvec, LF);
}

// round 6
// speedup vs baseline: 1.1613x; 1.1613x over previous
#include <cuda_runtime.h>
#include <cstdint>
#include <math.h>

#define NB 16384
#define NLOC 12
#define NF 512
#define NH 256
#define SCALE 0.0625f

// Scratch (device globals: allocation-free rule)
__device__ float g_T[(size_t)NB * NF];       // 32 MB
__device__ float g_pooled[(size_t)NB * NF];  // 32 MB
__device__ float g_lfG[(size_t)NB * NF];     // 32 MB
__device__ float g_M3[NF * NF];              // Wq @ Wk^T
__device__ float g_Mcat[2 * NF * NF];        // [Wv@Wf_top ; S*Wv@Wf_bot]
__device__ float g_c[NF];

__device__ __forceinline__ uint32_t f2tf(float x) {
    uint32_t y;
    asm("cvt.rna.tf32.f32 %0, %1;" : "=r"(y) : "f"(x));
    return y;
}

__device__ __forceinline__ void cpa16(void* dst_smem, const void* src) {
    uint32_t d = (uint32_t)__cvta_generic_to_shared(dst_smem);
    asm volatile("cp.async.cg.shared.global [%0], [%1], 16;" :: "r"(d), "l"(src));
}
__device__ __forceinline__ void cpa_commit() {
    asm volatile("cp.async.commit_group;");
}
template <int N>
__device__ __forceinline__ void cpa_wait() {
    asm volatile("cp.async.wait_group %0;" :: "n"(N));
}

__device__ __forceinline__ void mma8(float* c, const uint32_t* a, const uint32_t* b) {
    asm volatile(
        "mma.sync.aligned.m16n8k8.row.col.f32.tf32.tf32.f32 "
        "{%0,%1,%2,%3}, {%4,%5,%6,%7}, {%8,%9}, {%0,%1,%2,%3};"
        : "+f"(c[0]), "+f"(c[1]), "+f"(c[2]), "+f"(c[3])
        : "r"(a[0]), "r"(a[1]), "r"(a[2]), "r"(a[3]), "r"(b[0]), "r"(b[1]));
}

constexpr int BM = 128, BN = 64, BK = 16;
constexpr int ASTR = 20;  // floats per A smem row (bank-conflict-free frag loads)
constexpr int BSTR = 72;  // floats per B smem row (72 mod 32 == 8 -> conflict-free)
constexpr int STG = 3;    // 3-stage cp.async pipeline

// GEMM tile body: C[BMxBN at (by,bx)] = alpha * A[M,K] @ B[K,N]
// BT: B source is [N,K] (transposed), loaded via LDG+STS.
// CONCAT: A rows are [A | A2] along K (split at NF).
// FUSE: C = relu(acc + cvec[n]) + lfG[m,n].
template <bool BT, bool CONCAT, bool FUSE>
__device__ __forceinline__ void gemm_body(
    const float* __restrict__ A, int lda,
    const float* __restrict__ A2,
    const float* __restrict__ B, int ldb,
    float* __restrict__ C, int ldc,
    int K, float alpha,
    const float* __restrict__ cvec,
    const float* __restrict__ lfG,
    int bx, int by, float* sA, float* sB)
{
    const int tid = threadIdx.x;
    const int m0 = by * BM;
    const int n0 = bx * BN;
    const int warp = tid >> 5, lane = tid & 31;
    const int wm = warp & 3, wn = warp >> 2;   // 4 x 2 warp grid, 32x32 warp tile
    const int grp = lane >> 2, qid = lane & 3;

    const int ar0 = tid >> 2, ac0 = (tid & 3) * 4;
    const int ar1 = (tid + 256) >> 2;
    const int bk0 = tid >> 4, bn0 = (tid & 15) * 4;
    const int tn = tid >> 2, tk = (tid & 3) * 4;

    float acc[2][4][4];
#pragma unroll
    for (int i = 0; i < 2; i++)
#pragma unroll
        for (int j = 0; j < 4; j++)
#pragma unroll
            for (int l = 0; l < 4; l++) acc[i][j][l] = 0.f;

    const int niter = K / BK;

    auto issue = [&](int s, int k0) {
        const float* Ap = A;
        int kA = k0;
        if (CONCAT && k0 >= NF) { Ap = A2; kA = k0 - NF; }
        cpa16(&sA[((size_t)s * BM + ar0) * ASTR + ac0],
              Ap + (size_t)(m0 + ar0) * lda + kA + ac0);
        cpa16(&sA[((size_t)s * BM + ar1) * ASTR + ac0],
              Ap + (size_t)(m0 + ar1) * lda + kA + ac0);
        if (!BT) {
            cpa16(&sB[((size_t)s * BK + bk0) * BSTR + bn0],
                  B + (size_t)(k0 + bk0) * ldb + n0 + bn0);
        } else {
            float4 v = *(const float4*)(B + (size_t)(n0 + tn) * ldb + k0 + tk);
            sB[((size_t)s * BK + tk + 0) * BSTR + tn] = v.x;
            sB[((size_t)s * BK + tk + 1) * BSTR + tn] = v.y;
            sB[((size_t)s * BK + tk + 2) * BSTR + tn] = v.z;
            sB[((size_t)s * BK + tk + 3) * BSTR + tn] = v.w;
        }
        cpa_commit();
    };

    issue(0, 0);
    issue(1, BK);

    for (int it = 0; it < niter; it++) {
        const int cur = it % STG;
        if (it + 2 < niter) {
            issue((it + 2) % STG, (it + 2) * BK);
            cpa_wait<2>();
        } else if (it + 1 < niter) {
            cpa_wait<1>();
        } else {
            cpa_wait<0>();
        }
        __syncthreads();

        const float* As = &sA[(size_t)cur * BM * ASTR];
        const float* Bs = &sB[(size_t)cur * BK * BSTR];
#pragma unroll
        for (int kk = 0; kk < BK; kk += 8) {
            uint32_t a[2][4], b[4][2];
#pragma unroll
            for (int mi = 0; mi < 2; mi++) {
                int m = wm * 32 + mi * 16;
                a[mi][0] = f2tf(As[(m + grp) * ASTR + kk + qid]);
                a[mi][1] = f2tf(As[(m + grp + 8) * ASTR + kk + qid]);
                a[mi][2] = f2tf(As[(m + grp) * ASTR + kk + qid + 4]);
                a[mi][3] = f2tf(As[(m + grp + 8) * ASTR + kk + qid + 4]);
            }
#pragma unroll
            for (int ni = 0; ni < 4; ni++) {
                int n = wn * 32 + ni * 8;
                b[ni][0] = f2tf(Bs[(kk + qid) * BSTR + n + grp]);
                b[ni][1] = f2tf(Bs[(kk + qid + 4) * BSTR + n + grp]);
            }
#pragma unroll
            for (int mi = 0; mi < 2; mi++)
#pragma unroll
                for (int ni = 0; ni < 4; ni++) mma8(acc[mi][ni], a[mi], b[ni]);
        }
        __syncthreads();
    }

#pragma unroll
    for (int mi = 0; mi < 2; mi++) {
#pragma unroll
        for (int ni = 0; ni < 4; ni++) {
            int r = m0 + wm * 32 + mi * 16 + grp;
            int cn = n0 + wn * 32 + ni * 8 + qid * 2;
            size_t o0 = (size_t)r * ldc + cn;
            size_t o1 = (size_t)(r + 8) * ldc + cn;
            if (!FUSE) {
                float2 v0 = make_float2(alpha * acc[mi][ni][0], alpha * acc[mi][ni][1]);
                float2 v1 = make_float2(alpha * acc[mi][ni][2], alpha * acc[mi][ni][3]);
                *(float2*)(C + o0) = v0;
                *(float2*)(C + o1) = v1;
            } else {
                float c0 = cvec[cn], c1 = cvec[cn + 1];
                float2 v0, v1;
                v0.x = fmaxf(acc[mi][ni][0] + c0, 0.f) + lfG[o0];
                v0.y = fmaxf(acc[mi][ni][1] + c1, 0.f) + lfG[o0 + 1];
                v1.x = fmaxf(acc[mi][ni][2] + c0, 0.f) + lfG[o1];
                v1.y = fmaxf(acc[mi][ni][3] + c1, 0.f) + lfG[o1 + 1];
                *(float2*)(C + o0) = v0;
                *(float2*)(C + o1) = v1;
            }
        }
    }
}

// Big GEMM wrapper. Grid: x = N-tile (fast -> L2 A reuse), y = M-tile.
template <bool CONCAT, bool FUSE>
__global__ __launch_bounds__(256, 2) void gemm_big(
    const float* __restrict__ A, int lda,
    const float* __restrict__ A2,
    const float* __restrict__ B, int ldb,
    float* __restrict__ C, int ldc, int K,
    const float* __restrict__ cvec,
    const float* __restrict__ lfG)
{
    __shared__ float sA[STG * BM * ASTR];
    __shared__ float sB[STG * BK * BSTR];
    gemm_body<false, CONCAT, FUSE>(A, lda, A2, B, ldb, C, ldc, K, 1.f,
                                   cvec, lfG, blockIdx.x, blockIdx.y, sA, sB);
}

// Fused precompute: blocks 0-31 M3 = Wq@Wk^T; 32-63 Mcat_top = Wv@Wf_top;
// 64-95 Mcat_bot = S * Wv@Wf_bot; 96-103 cvec reduction.
__global__ __launch_bounds__(256, 2) void k_pre(
    const float* __restrict__ Wq, const float* __restrict__ Wk,
    const float* __restrict__ Wv, const float* __restrict__ bv,
    const float* __restrict__ Wf, const float* __restrict__ bf,
    const float* __restrict__ wdr, const float* __restrict__ bdr)
{
    __shared__ float sA[STG * BM * ASTR];
    __shared__ float sB[STG * BK * BSTR];
    const int b = blockIdx.x;
    if (b < 96) {
        const int g = b & 31;
        const int bx = g & 7, by = g >> 3;   // 8 N-tiles x 4 M-tiles
        if (b < 32) {
            gemm_body<true, false, false>(Wq, NH, nullptr, Wk, NH, g_M3, NF, NH,
                                          1.f, nullptr, nullptr, bx, by, sA, sB);
        } else if (b < 64) {
            gemm_body<false, false, false>(Wv, NH, nullptr, Wf, NF, g_Mcat, NF, NH,
                                           1.f, nullptr, nullptr, bx, by, sA, sB);
        } else {
            float S = 0.f;
#pragma unroll
            for (int k = 0; k < NLOC; k++) S += wdr[k];
            gemm_body<false, false, false>(Wv, NH, nullptr, Wf + (size_t)NH * NF, NF,
                                           g_Mcat + (size_t)NF * NF, NF, NH,
                                           S, nullptr, nullptr, bx, by, sA, sB);
        }
    } else {
        // cvec: c[f] = bf + bv@Wf_top + S*bv@Wf_bot + b_dr*colsum(Wf_bot)
        __shared__ float red[3][4][64];
        const int t = threadIdx.x;
        const int fl = t & 63;            // local f within this block's 64-column slice
        const int f = (b - 96) * 64 + fl;
        const int hc = t >> 6;            // h-chunk 0..3
        float a1 = 0.f, a2 = 0.f, a3 = 0.f;
        for (int h = hc * 64; h < hc * 64 + 64; h++) {
            float w1 = Wf[(size_t)h * NF + f];
            float w2 = Wf[(size_t)(NH + h) * NF + f];
            float bvh = bv[h];
            a1 += bvh * w1;
            a2 += bvh * w2;
            a3 += w2;
        }
        red[0][hc][fl] = a1;
        red[1][hc][fl] = a2;
        red[2][hc][fl] = a3;
        __syncthreads();
        if (hc == 0) {
            float s1 = red[0][0][fl] + red[0][1][fl] + red[0][2][fl] + red[0][3][fl];
            float s2 = red[1][0][fl] + red[1][1][fl] + red[1][2][fl] + red[1][3][fl];
            float s3 = red[2][0][fl] + red[2][1][fl] + red[2][2][fl] + red[2][3][fl];
            float S = 0.f;
#pragma unroll
            for (int k = 0; k < NLOC; k++) S += wdr[k];
            g_c[f] = bf[f] + s1 + S * s2 + (*bdr) * s3;
        }
    }
}

// Per-row: scores vs T, softmax over 12, pooled = sum a_k * local_k,
// lfG = sum w_dr_k * local_k + b_dr + G   (local read exactly once via smem)
__global__ __launch_bounds__(128) void k_attn(
    const float* __restrict__ G, const float* __restrict__ L,
    const float* __restrict__ wdr, const float* __restrict__ bdr)
{
    __shared__ float4 sL[NLOC * 128];
    __shared__ float4 sT[128];
    __shared__ float sd[NLOC];
    const int b = blockIdx.x, tid = threadIdx.x;
    const float4* Lr = (const float4*)(L + (size_t)b * NLOC * NF);
    sT[tid] = ((const float4*)(g_T + (size_t)b * NF))[tid];
#pragma unroll
    for (int k = 0; k < NLOC; k++) sL[k * 128 + tid] = Lr[k * 128 + tid];
    __syncthreads();

    const int warp = tid >> 5, lane = tid & 31;
#pragma unroll
    for (int kk = 0; kk < 3; kk++) {
        int k = warp * 3 + kk;
        float s = 0.f;
#pragma unroll
        for (int j = 0; j < 4; j++) {
            float4 x = sL[k * 128 + lane + j * 32];
            float4 t = sT[lane + j * 32];
            s += x.x * t.x + x.y * t.y + x.z * t.z + x.w * t.w;
        }
#pragma unroll
        for (int o = 16; o; o >>= 1) s += __shfl_xor_sync(0xffffffffu, s, o);
        if (lane == 0) sd[k] = s;
    }
    __syncthreads();

    float a[NLOC], mx = -1e30f;
#pragma unroll
    for (int k = 0; k < NLOC; k++) mx = fmaxf(mx, sd[k]);
    float sum = 0.f;
#pragma unroll
    for (int k = 0; k < NLOC; k++) { a[k] = __expf((sd[k] - mx) * SCALE); sum += a[k]; }
    float inv = 1.f / sum;

    float4 p = make_float4(0, 0, 0, 0), q = make_float4(0, 0, 0, 0);
#pragma unroll
    for (int k = 0; k < NLOC; k++) {
        float ak = a[k] * inv, wk = wdr[k];
        float4 x = sL[k * 128 + tid];
        p.x += ak * x.x; p.y += ak * x.y; p.z += ak * x.z; p.w += ak * x.w;
        q.x += wk * x.x; q.y += wk * x.y; q.z += wk * x.z; q.w += wk * x.w;
    }
    float bd = *bdr;
    float4 g = ((const float4*)(G + (size_t)b * NF))[tid];
    ((float4*)(g_pooled + (size_t)b * NF))[tid] = p;
    float4 o;
    o.x = q.x + bd + g.x; o.y = q.y + bd + g.y;
    o.z = q.z + bd + g.z; o.w = q.w + bd + g.w;
    ((float4*)(g_lfG + (size_t)b * NF))[tid] = o;
}

extern "C" void kernel_launch(void* const* d_in, const int* in_sizes, int n_in,
                              void* d_out, int out_size)
{
    const float* G   = (const float*)d_in[0];
    const float* L   = (const float*)d_in[1];
    const float* Wq  = (const float*)d_in[2];
    // d_in[3] = bq (unused: drops out of softmax)
    const float* Wk  = (const float*)d_in[4];
    // d_in[5] = bk (unused: k-independent score shift cancels in softmax)
    const float* Wv  = (const float*)d_in[6];
    const float* bv  = (const float*)d_in[7];
    const float* wdr = (const float*)d_in[8];
    const float* bdr = (const float*)d_in[9];
    const float* Wf  = (const float*)d_in[10];
    const float* bf  = (const float*)d_in[11];
    float* out = (float*)d_out;

    float *T, *P, *LF, *M3, *Mcat, *cvec;
    cudaGetSymbolAddress((void**)&T, g_T);
    cudaGetSymbolAddress((void**)&P, g_pooled);
    cudaGetSymbolAddress((void**)&LF, g_lfG);
    cudaGetSymbolAddress((void**)&M3, g_M3);
    cudaGetSymbolAddress((void**)&Mcat, g_Mcat);
    cudaGetSymbolAddress((void**)&cvec, g_c);

    dim3 blk(256);
    dim3 gbig(NF / 64, NB / 128);   // x = N-tiles (8), y = M-tiles (128)

    // 1) fused precompute: M3, Mcat (both halves), cvec   [104 blocks, one launch]
    k_pre<<<104, blk>>>(Wq, Wk, Wv, bv, Wf, bf, wdr, bdr);

    // 2) T = G @ M3   [16384,512] x [512,512]
    gemm_big<false, false><<<gbig, blk>>>(
        G, NF, nullptr, M3, NF, T, NF, NF, nullptr, nullptr);

    // 3) per-row softmax / pooling (reads local_features once)
    k_attn<<<NB, 128>>>(G, L, wdr, bdr);

    // 4) OUT = relu([pooled | G] @ Mcat + c) + lfG   [16384,1024] x [1024,512]
    gemm_big<true, true><<<gbig, blk>>>(
        P, NF, G, Mcat, NF, out, NF, 2 * NF, cvec, LF);
}